// round 10
// baseline (speedup 1.0000x reference)
#include <cuda_runtime.h>
#include <cstdint>

#define NB 8
#define NP 2048
#define NCF 1024
#define NCLS 3

// ---------------- scratch (__device__ globals; no allocation allowed) ----------------
__device__ float4 g_xy[NB][NP / 2];                // sorted SoA pairs {x0,x1,y0,y1}
__device__ float2 g_z[NB][NP / 2];                 // sorted SoA pairs {z0,z1}
__device__ int    g_lab[NB][NP];                   // sorted labels
__device__ float  g_L[NB][NP];                     // exact squared-radius threshold
__device__ int    g_sidx[NB][NP];                  // sorted -> original index
__device__ unsigned long long g_mask[NB][NP][32];  // suppression bitmask rows (4MB)
__device__ unsigned char g_keep[NB * NP];          // keep flags by original index

// packed f32x2 helpers (two independent RN ops -> bit-identical to scalar RN)
__device__ __forceinline__ unsigned long long f2add(unsigned long long a, unsigned long long b) {
    unsigned long long r;
    asm("add.rn.f32x2 %0, %1, %2;" : "=l"(r) : "l"(a), "l"(b));
    return r;
}
__device__ __forceinline__ unsigned long long f2mul(unsigned long long a, unsigned long long b) {
    unsigned long long r;
    asm("mul.rn.f32x2 %0, %1, %2;" : "=l"(r) : "l"(a), "l"(b));
    return r;
}
__device__ __forceinline__ unsigned long long pk2(float a, float b) {
    unsigned long long r;
    asm("mov.b64 %0, {%1, %2};" : "=l"(r) : "f"(a), "f"(b));
    return r;
}

// ---------------- K1: rank-by-counting sort (score desc, idx asc) ----------------
__global__ __launch_bounds__(256) void k1_rank(const float* __restrict__ centers,
                                               const float* __restrict__ cls,
                                               const float* __restrict__ radius)
{
    __shared__ unsigned long long keys[NP];  // 16KB
    const int b = blockIdx.y;
    const int tid = threadIdx.x;

    for (int p = tid; p < NP; p += 256) {
        const float* cp = cls + ((size_t)b * NP + p) * NCLS;
        float c0 = cp[0], c1 = cp[1], c2 = cp[2];
        float s = c0;
        if (c1 > s) s = c1;
        if (c2 > s) s = c2;
        unsigned su = __float_as_uint(s);
        unsigned ord = su ^ ((su & 0x80000000u) ? 0xFFFFFFFFu : 0x80000000u);
        // ascending key order => score descending, index ascending (argmax tie-break)
        keys[p] = ((unsigned long long)(~ord) << 32) | (unsigned)p;
    }
    __syncthreads();

    const int warp = tid >> 5, lane = tid & 31;
    const int pbase = blockIdx.x * 32 + warp * 4;

    const unsigned long long k0 = keys[pbase + 0];
    const unsigned long long k1 = keys[pbase + 1];
    const unsigned long long k2 = keys[pbase + 2];
    const unsigned long long k3 = keys[pbase + 3];
    int r0 = 0, r1 = 0, r2 = 0, r3 = 0;
    #pragma unroll 4
    for (int j = lane; j < NP; j += 32) {
        unsigned long long kj = keys[j];
        r0 += (kj < k0);
        r1 += (kj < k1);
        r2 += (kj < k2);
        r3 += (kj < k3);
    }
    r0 = __reduce_add_sync(0xFFFFFFFFu, r0);
    r1 = __reduce_add_sync(0xFFFFFFFFu, r1);
    r2 = __reduce_add_sync(0xFFFFFFFFu, r2);
    r3 = __reduce_add_sync(0xFFFFFFFFu, r3);

    if (lane < 4) {
        int p = pbase + lane;
        int rank = (lane == 0) ? r0 : (lane == 1) ? r1 : (lane == 2) ? r2 : r3;

        const float* cp = cls + ((size_t)b * NP + p) * NCLS;
        float c0 = cp[0], c1 = cp[1], c2 = cp[2];
        int lab = 0; float s = c0;
        if (c1 > s) { s = c1; lab = 1; }
        if (c2 > s) { s = c2; lab = 2; }

        const float* cc = centers + ((size_t)b * NP + p) * 3;
        float x = cc[0], y = cc[1], z = cc[2];

        // Exact threshold: RN(sqrt(d2)) < r  <=>  d2 <= L, where
        // L = largest f32 strictly below M = ((pred(r)+r)/2)^2 (real arithmetic).
        float r = radius[lab];
        float L;
        if (!(r > 0.0f)) {
            L = -1.0f;
        } else {
            float pr = __uint_as_float(__float_as_uint(r) - 1u);
            double m = 0.5 * ((double)pr + (double)r);
            double M = m * m;
            float f = (float)M;
            if ((double)f < M) L = f;
            else L = __uint_as_float(__float_as_uint(f) - 1u);
        }

        int pr2 = rank >> 1, c = rank & 1;
        float* xy = (float*)&g_xy[b][0];
        xy[pr2 * 4 + c] = x;
        xy[pr2 * 4 + 2 + c] = y;
        ((float*)&g_z[b][0])[pr2 * 2 + c] = z;
        g_lab[b][rank] = lab;
        g_L[b][rank] = L;
        g_sidx[b][rank] = p;
    }
}

// ---------------- K2: suppression bit-matrix, triangle-balanced ----------------
// grid (32, 8), 256 threads = 8 warps. Pair p owns row-warps p and 63-p: the
// upper-triangle word jobs of the pair always total 33; warp w takes jobs
// w, w+8, w+16, ... -> uniform ~4 jobs/warp across the whole grid.
__global__ __launch_bounds__(256) void k2_mask()
{
    __shared__ ulonglong2 sxy[NP / 2];          // 16KB {xpair, ypair}
    __shared__ unsigned long long szp[NP / 2];  // 8KB  {zpair}
    __shared__ int slab[NP];                    // 8KB
    __shared__ float sL[NP];                    // 8KB
    __shared__ unsigned long long cbits[3][32]; // class membership bitmasks

    const int b = blockIdx.y;
    const int tid = threadIdx.x;

    for (int k = tid; k < NP / 2; k += 256) {
        sxy[k] = ((const ulonglong2*)&g_xy[b][0])[k];
        szp[k] = ((const unsigned long long*)&g_z[b][0])[k];
    }
    for (int k = tid; k < NP; k += 256) {
        slab[k] = g_lab[b][k];
        sL[k] = g_L[b][k];
    }
    __syncthreads();

    if (tid < 96) {
        int c = tid >> 5, w = tid & 31;
        unsigned long long m = 0ull;
        #pragma unroll 8
        for (int jj = 0; jj < 64; jj++)
            m |= (unsigned long long)(slab[w * 64 + jj] == c) << jj;
        cbits[c][w] = m;
    }
    __syncthreads();

    const int warp = tid >> 5, lane = tid & 31;
    const int rwA = blockIdx.x, rwB = 63 - blockIdx.x;
    const int c1 = 32 - (rwA >> 1), c2 = 32 - (rwB >> 1);

    for (int job = warp; job < c1 + c2; job += 8) {
        int rw, jc;
        if (job < c1) { rw = rwA; jc = (rwA >> 1) + job; }
        else          { rw = rwB; jc = (rwB >> 1) + (job - c1); }

        const int i = rw * 32 + lane;
        const float xi = ((const float*)&sxy[0])[(i >> 1) * 4 + (i & 1)];
        const float yi = ((const float*)&sxy[0])[(i >> 1) * 4 + 2 + (i & 1)];
        const float zi = ((const float*)&szp[0])[(i >> 1) * 2 + (i & 1)];
        const int li = slab[i];
        const float Li = sL[i];

        const unsigned long long nmx = pk2(-xi, -xi);
        const unsigned long long nmy = pk2(-yi, -yi);
        const unsigned long long nmz = pk2(-zi, -zi);
        const unsigned long long Lp  = pk2(Li, Li);

        unsigned long long bits = 0ull;
        const int jb = jc * 32;
        #pragma unroll 8
        for (int q = 0; q < 32; q++) {
            ulonglong2 v = sxy[jb + q];
            unsigned long long zp = szp[jb + q];
            // dq = q - me (negated diff; squares identical to reference)
            unsigned long long dx = f2add(v.x, nmx);
            unsigned long long dy = f2add(v.y, nmy);
            unsigned long long dz = f2add(zp, nmz);
            unsigned long long x2 = f2mul(dx, dx);
            unsigned long long y2 = f2mul(dy, dy);
            unsigned long long z2 = f2mul(dz, dz);
            // match XLA: (dx*dx + dy*dy) + dz*dz
            unsigned long long d2 = f2add(f2add(x2, y2), z2);
            // t = Li - d2; suppress iff sign(t)==0  (<=> d2 <= Li exactly)
            unsigned long long t = f2add(Lp, d2 ^ 0x8000000080000000ull);
            unsigned tlo = (unsigned)t;
            unsigned thi = (unsigned)(t >> 32);
            bits |= (unsigned long long)((~tlo) >> 31) << (2 * q);
            bits |= (unsigned long long)((~thi) >> 31) << (2 * q + 1);
        }
        g_mask[b][i][jc] = bits & cbits[li][jc];
    }
}

// ---------------- K3: warp-specialized pipelined greedy scan ----------------
// One 256-thread block per scene. Chunk c only ever reads mask words >= c-1,
// so prefetch starts at word ws(n) = even-floor(n-1); the OR phase guards
// lane >= vstart so no stale shared data can reach srem (words in that range
// not written by k2 are zero-initialized device globals -> contribute 0).
// The serial diagonal early-exits per 8-row group once no alive rows remain
// (kept rows self-clear their bit via the diagonal self-suppress bit).
#define RSTRIDE 34  // u64 per row (32 data + 2 pad): 272B, 16B-aligned rows
__device__ __forceinline__ int k3_ws(int n) { return (n <= 1) ? 0 : ((n - 1) & ~1); }

__global__ __launch_bounds__(256) void k3_scan(float* __restrict__ out_keep)
{
    __shared__ __align__(16) unsigned long long buf[4][64][RSTRIDE];  // ~68KB
    __shared__ unsigned long long srem[32];
    __shared__ unsigned long long part[7][32];
    __shared__ unsigned long long skeep[2];
    __shared__ int ssidx[NP];  // 8KB

    const int b = blockIdx.x;
    const int tid = threadIdx.x;
    const int warp = tid >> 5, lane = tid & 31;

    for (int k = tid; k < NP; k += 256) ssidx[k] = g_sidx[b][k];
    if (tid < 32) srem[tid] = 0ull;
    if (tid == 0) { skeep[0] = 0ull; skeep[1] = 0ull; }

    // prefetch chunks 0 and 1: copy words [ws(n), 32) of chunk n into slot n
    #pragma unroll
    for (int ch = 0; ch < 2; ch++) {
        const int ws = k3_ws(ch), vpr = (32 - ws) >> 1;
        const float4* srcb = (const float4*)&g_mask[b][ch * 64][0];
        for (int v = tid; v < 64 * vpr; v += 256) {
            int row = v / vpr, cv = (v % vpr) + (ws >> 1);
            float4* dst = (float4*)&buf[ch][row][0] + cv;
            unsigned sa = (unsigned)__cvta_generic_to_shared(dst);
            asm volatile("cp.async.cg.shared.global [%0], [%1], 16;\n"
                         :: "r"(sa), "l"(srcb + row * 16 + cv) : "memory");
        }
        asm volatile("cp.async.commit_group;\n" ::: "memory");
    }
    asm volatile("cp.async.wait_group 1;\n" ::: "memory");  // chunk 0 retired

    for (int c = 0; c < 32; c++) {
        __syncthreads();  // chunk c visible; prev OR & keep published; ring slot free

        if (c < 30) {
            const int n = c + 2, slot = n & 3;
            const int ws = k3_ws(n), vpr = (32 - ws) >> 1;
            const float4* srcb = (const float4*)&g_mask[b][n * 64][0];
            for (int v = tid; v < 64 * vpr; v += 256) {
                int row = v / vpr, cv = (v % vpr) + (ws >> 1);
                float4* dst = (float4*)&buf[slot][row][0] + cv;
                unsigned sa = (unsigned)__cvta_generic_to_shared(dst);
                asm volatile("cp.async.cg.shared.global [%0], [%1], 16;\n"
                             :: "r"(sa), "l"(srcb + row * 16 + cv) : "memory");
            }
        }
        asm volatile("cp.async.commit_group;\n" ::: "memory");  // always (maybe empty)

        const int cur = c & 3, prv = (c + 3) & 3;
        const unsigned long long kprev = skeep[(c & 1) ^ 1];  // chunk c-1 keep (0 for c=0)

        if (warp == 0) {
            // forward word: chunk c-1 kept rows' contribution to removed word c
            unsigned long long f = 0ull;
            if (kprev) {
                unsigned long long m0 = (unsigned long long)(-(long long)((kprev >> lane) & 1ull));
                unsigned long long m1 = (unsigned long long)(-(long long)((kprev >> (lane + 32)) & 1ull));
                f = (buf[prv][lane][c] & m0) | (buf[prv][lane + 32][c] & m1);
                #pragma unroll
                for (int off = 16; off > 0; off >>= 1)
                    f |= __shfl_xor_sync(0xFFFFFFFFu, f, off);
            }

            if (lane == 0) {
                unsigned long long rm = srem[c] | f;  // concurrent srem[c] update is benign:
                                                      // it only adds bits identical to f
                unsigned lo = ~(unsigned)rm;
                unsigned hi = ~(unsigned)(rm >> 32);
                unsigned klo = 0, khi = 0;
                if (lo) {
                    #pragma unroll
                    for (int g = 0; g < 4; g++) {
                        #pragma unroll
                        for (int k = 0; k < 8; k++) {
                            int r = g * 8 + k;
                            unsigned s = (unsigned)((int)(lo << (31 - r)) >> 31);
                            klo |= s & (1u << r);
                            unsigned long long d = buf[cur][r][c];
                            lo &= ~((unsigned)d & s);
                            hi &= ~((unsigned)(d >> 32) & s);
                        }
                        if (!lo) break;  // kept rows self-clear => lo==0 means done
                    }
                }
                if (hi) {
                    #pragma unroll
                    for (int g = 0; g < 4; g++) {
                        #pragma unroll
                        for (int k = 0; k < 8; k++) {
                            int r = g * 8 + k;
                            unsigned s = (unsigned)((int)(hi << (31 - r)) >> 31);
                            khi |= s & (1u << r);
                            hi &= ~((unsigned)(buf[cur][32 + r][c] >> 32) & s);
                        }
                        if (!hi) break;
                    }
                }
                skeep[c & 1] = ((unsigned long long)khi << 32) | klo;
            }
        } else {
            // OR phase for chunk c-1 into srem (skip entirely when nothing kept);
            // kprev is uniform across warps 1-7 -> bar.sync below is convergent
            if (kprev) {
                const int w = warp - 1;  // 0..6
                const int vstart = k3_ws(c - 1);  // valid words of prv chunk
                unsigned long long p = 0ull;
                if (lane >= vstart) {
                    for (int r = w; r < 64; r += 7) {
                        unsigned long long m =
                            (unsigned long long)(-(long long)((kprev >> r) & 1ull));
                        p |= buf[prv][r][lane] & m;
                    }
                }
                part[w][lane] = p;
                asm volatile("bar.sync 1, 224;" ::: "memory");
                if (warp == 1) {
                    srem[lane] |= (part[0][lane] | part[1][lane]) |
                                  (part[2][lane] | part[3][lane]) |
                                  (part[4][lane] | part[5][lane]) | part[6][lane];
                }
            }
            if (warp == 2 && c > 0) {
                int row = (c - 1) * 64 + lane;
                int oi = ssidx[row];
                unsigned bit = (unsigned)((kprev >> lane) & 1ull);
                g_keep[b * NP + oi] = (unsigned char)bit;
                out_keep[b * NP + oi] = bit ? 1.0f : 0.0f;
                int row2 = row + 32;
                int oi2 = ssidx[row2];
                unsigned bit2 = (unsigned)((kprev >> (lane + 32)) & 1ull);
                g_keep[b * NP + oi2] = (unsigned char)bit2;
                out_keep[b * NP + oi2] = bit2 ? 1.0f : 0.0f;
            }
        }
        asm volatile("cp.async.wait_group 1;\n" ::: "memory");  // retire chunk c+1's group
    }
    __syncthreads();
    if (tid < 64) {  // outputs for chunk 31 (skeep[31&1] = skeep[1])
        unsigned long long k31 = skeep[1];
        int row = 31 * 64 + tid;
        int oi = ssidx[row];
        unsigned bit = (unsigned)((k31 >> tid) & 1ull);
        g_keep[b * NP + oi] = (unsigned char)bit;
        out_keep[b * NP + oi] = bit ? 1.0f : 0.0f;
    }
}

// ---------------- K4: apply keep mask, 4 independent float4 per thread ----------------
// out layout (floats): centers @0 (49152) | features @49152 (16777216) |
//                      cls @16826368 (49152) | keep @16875520 (16384, written by K3)
__global__ __launch_bounds__(256) void k4_apply(const float* __restrict__ centers,
                                                const float* __restrict__ features,
                                                const float* __restrict__ cls,
                                                float* __restrict__ out)
{
    const int NF4q = NB * NP * NCF / 16;  // 1048576: quarter of the float4 tasks
    int t = blockIdx.x * 256 + threadIdx.x;
    if (t < NF4q) {
        #pragma unroll
        for (int k = 0; k < 4; k++) {
            int ti = t + k * NF4q;
            bool kp = g_keep[ti >> 8] != 0;  // block maps to one point -> uniform
            float4 v = make_float4(0.f, 0.f, 0.f, 0.f);
            if (kp) v = __ldcs(((const float4*)features) + ti);
            __stcs(((float4*)out) + 12288 + ti, v);  // 49152/4 offset
        }
    } else {
        int s = t - NF4q;
        if (s < NB * NP * 3) {
            int pg = s / 3;
            out[s] = g_keep[pg] ? centers[s] : 0.0f;
        } else {
            int e = s - NB * NP * 3;
            int pg = e / 3;
            out[16826368 + e] = g_keep[pg] ? cls[e] : 0.0f;
        }
    }
}

extern "C" void kernel_launch(void* const* d_in, const int* in_sizes, int n_in,
                              void* d_out, int out_size)
{
    const float* centers  = (const float*)d_in[0];
    const float* features = (const float*)d_in[1];
    const float* cls      = (const float*)d_in[2];
    const float* radius   = (const float*)d_in[3];
    float* out = (float*)d_out;

    k1_rank<<<dim3(64, NB), 256>>>(centers, cls, radius);
    k2_mask<<<dim3(32, NB), 256>>>();
    k3_scan<<<NB, 256>>>(out + 16875520);
    const int total = NB * NP * NCF / 16 + 2 * NB * NP * 3;  // 1146880
    k4_apply<<<total / 256, 256>>>(centers, features, cls, out);
}

// round 11
// speedup vs baseline: 1.1955x; 1.1955x over previous
#include <cuda_runtime.h>
#include <cstdint>

#define NB 8
#define NP 2048
#define NCF 1024
#define NCLS 3

// ---------------- scratch (__device__ globals; no allocation allowed) ----------------
__device__ float4 g_xy[NB][NP / 2];                // sorted SoA pairs {x0,x1,y0,y1}
__device__ float2 g_z[NB][NP / 2];                 // sorted SoA pairs {z0,z1}
__device__ int    g_lab[NB][NP];                   // sorted labels
__device__ float  g_L[NB][NP];                     // exact squared-radius threshold
__device__ int    g_sidx[NB][NP];                  // sorted -> original index
__device__ unsigned long long g_mask[NB][NP][32];  // suppression bitmask rows (4MB)
__device__ unsigned char g_keep[NB * NP];          // keep flags by original index

// packed f32x2 helpers (two independent RN ops -> bit-identical to scalar RN)
__device__ __forceinline__ unsigned long long f2add(unsigned long long a, unsigned long long b) {
    unsigned long long r;
    asm("add.rn.f32x2 %0, %1, %2;" : "=l"(r) : "l"(a), "l"(b));
    return r;
}
__device__ __forceinline__ unsigned long long f2mul(unsigned long long a, unsigned long long b) {
    unsigned long long r;
    asm("mul.rn.f32x2 %0, %1, %2;" : "=l"(r) : "l"(a), "l"(b));
    return r;
}
__device__ __forceinline__ unsigned long long pk2(float a, float b) {
    unsigned long long r;
    asm("mov.b64 %0, {%1, %2};" : "=l"(r) : "f"(a), "f"(b));
    return r;
}

// ---------------- K1: rank-by-counting sort (score desc, idx asc) ----------------
__global__ __launch_bounds__(256) void k1_rank(const float* __restrict__ centers,
                                               const float* __restrict__ cls,
                                               const float* __restrict__ radius)
{
    __shared__ unsigned long long keys[NP];  // 16KB
    const int b = blockIdx.y;
    const int tid = threadIdx.x;

    for (int p = tid; p < NP; p += 256) {
        const float* cp = cls + ((size_t)b * NP + p) * NCLS;
        float c0 = cp[0], c1 = cp[1], c2 = cp[2];
        float s = c0;
        if (c1 > s) s = c1;
        if (c2 > s) s = c2;
        unsigned su = __float_as_uint(s);
        unsigned ord = su ^ ((su & 0x80000000u) ? 0xFFFFFFFFu : 0x80000000u);
        // ascending key order => score descending, index ascending (argmax tie-break)
        keys[p] = ((unsigned long long)(~ord) << 32) | (unsigned)p;
    }
    __syncthreads();

    const int warp = tid >> 5, lane = tid & 31;
    const int pbase = blockIdx.x * 32 + warp * 4;

    const unsigned long long k0 = keys[pbase + 0];
    const unsigned long long k1 = keys[pbase + 1];
    const unsigned long long k2 = keys[pbase + 2];
    const unsigned long long k3 = keys[pbase + 3];
    int r0 = 0, r1 = 0, r2 = 0, r3 = 0;
    #pragma unroll 4
    for (int j = lane; j < NP; j += 32) {
        unsigned long long kj = keys[j];
        r0 += (kj < k0);
        r1 += (kj < k1);
        r2 += (kj < k2);
        r3 += (kj < k3);
    }
    r0 = __reduce_add_sync(0xFFFFFFFFu, r0);
    r1 = __reduce_add_sync(0xFFFFFFFFu, r1);
    r2 = __reduce_add_sync(0xFFFFFFFFu, r2);
    r3 = __reduce_add_sync(0xFFFFFFFFu, r3);

    if (lane < 4) {
        int p = pbase + lane;
        int rank = (lane == 0) ? r0 : (lane == 1) ? r1 : (lane == 2) ? r2 : r3;

        const float* cp = cls + ((size_t)b * NP + p) * NCLS;
        float c0 = cp[0], c1 = cp[1], c2 = cp[2];
        int lab = 0; float s = c0;
        if (c1 > s) { s = c1; lab = 1; }
        if (c2 > s) { s = c2; lab = 2; }

        const float* cc = centers + ((size_t)b * NP + p) * 3;
        float x = cc[0], y = cc[1], z = cc[2];

        // Exact threshold: RN(sqrt(d2)) < r  <=>  d2 <= L, where
        // L = largest f32 strictly below M = ((pred(r)+r)/2)^2 (real arithmetic).
        float r = radius[lab];
        float L;
        if (!(r > 0.0f)) {
            L = -1.0f;
        } else {
            float pr = __uint_as_float(__float_as_uint(r) - 1u);
            double m = 0.5 * ((double)pr + (double)r);
            double M = m * m;
            float f = (float)M;
            if ((double)f < M) L = f;
            else L = __uint_as_float(__float_as_uint(f) - 1u);
        }

        int pr2 = rank >> 1, c = rank & 1;
        float* xy = (float*)&g_xy[b][0];
        xy[pr2 * 4 + c] = x;
        xy[pr2 * 4 + 2 + c] = y;
        ((float*)&g_z[b][0])[pr2 * 2 + c] = z;
        g_lab[b][rank] = lab;
        g_L[b][rank] = L;
        g_sidx[b][rank] = p;
    }
}

// ---------------- K2: suppression bit-matrix, triangle-balanced ----------------
// grid (32, 8), 256 threads = 8 warps. Pair p owns row-warps p and 63-p: the
// upper-triangle word jobs of the pair always total 33; warp w takes jobs
// w, w+8, w+16, ... -> uniform ~4 jobs/warp across the whole grid.
__global__ __launch_bounds__(256) void k2_mask()
{
    __shared__ ulonglong2 sxy[NP / 2];          // 16KB {xpair, ypair}
    __shared__ unsigned long long szp[NP / 2];  // 8KB  {zpair}
    __shared__ int slab[NP];                    // 8KB
    __shared__ float sL[NP];                    // 8KB
    __shared__ unsigned long long cbits[3][32]; // class membership bitmasks

    const int b = blockIdx.y;
    const int tid = threadIdx.x;

    for (int k = tid; k < NP / 2; k += 256) {
        sxy[k] = ((const ulonglong2*)&g_xy[b][0])[k];
        szp[k] = ((const unsigned long long*)&g_z[b][0])[k];
    }
    for (int k = tid; k < NP; k += 256) {
        slab[k] = g_lab[b][k];
        sL[k] = g_L[b][k];
    }
    __syncthreads();

    if (tid < 96) {
        int c = tid >> 5, w = tid & 31;
        unsigned long long m = 0ull;
        #pragma unroll 8
        for (int jj = 0; jj < 64; jj++)
            m |= (unsigned long long)(slab[w * 64 + jj] == c) << jj;
        cbits[c][w] = m;
    }
    __syncthreads();

    const int warp = tid >> 5, lane = tid & 31;
    const int rwA = blockIdx.x, rwB = 63 - blockIdx.x;
    const int c1 = 32 - (rwA >> 1), c2 = 32 - (rwB >> 1);

    for (int job = warp; job < c1 + c2; job += 8) {
        int rw, jc;
        if (job < c1) { rw = rwA; jc = (rwA >> 1) + job; }
        else          { rw = rwB; jc = (rwB >> 1) + (job - c1); }

        const int i = rw * 32 + lane;
        const float xi = ((const float*)&sxy[0])[(i >> 1) * 4 + (i & 1)];
        const float yi = ((const float*)&sxy[0])[(i >> 1) * 4 + 2 + (i & 1)];
        const float zi = ((const float*)&szp[0])[(i >> 1) * 2 + (i & 1)];
        const int li = slab[i];
        const float Li = sL[i];

        const unsigned long long nmx = pk2(-xi, -xi);
        const unsigned long long nmy = pk2(-yi, -yi);
        const unsigned long long nmz = pk2(-zi, -zi);
        const unsigned long long Lp  = pk2(Li, Li);

        unsigned long long bits = 0ull;
        const int jb = jc * 32;
        #pragma unroll 8
        for (int q = 0; q < 32; q++) {
            ulonglong2 v = sxy[jb + q];
            unsigned long long zp = szp[jb + q];
            // dq = q - me (negated diff; squares identical to reference)
            unsigned long long dx = f2add(v.x, nmx);
            unsigned long long dy = f2add(v.y, nmy);
            unsigned long long dz = f2add(zp, nmz);
            unsigned long long x2 = f2mul(dx, dx);
            unsigned long long y2 = f2mul(dy, dy);
            unsigned long long z2 = f2mul(dz, dz);
            // match XLA: (dx*dx + dy*dy) + dz*dz
            unsigned long long d2 = f2add(f2add(x2, y2), z2);
            // t = Li - d2; suppress iff sign(t)==0  (<=> d2 <= Li exactly)
            unsigned long long t = f2add(Lp, d2 ^ 0x8000000080000000ull);
            unsigned tlo = (unsigned)t;
            unsigned thi = (unsigned)(t >> 32);
            bits |= (unsigned long long)((~tlo) >> 31) << (2 * q);
            bits |= (unsigned long long)((~thi) >> 31) << (2 * q + 1);
        }
        g_mask[b][i][jc] = bits & cbits[li][jc];
    }
}

// ---------------- K3: warp-specialized pipelined greedy scan (R6 form + REDUX) ----
// One 256-thread block per scene. Per iteration c:
//   warp 0: forward-word (chunk c-1 contribution to removed word c, REDUX.OR) +
//           serial 64x64 diagonal for chunk c (batch-loaded regs, pure-ALU chain)
//   warps 1-7: OR chunk c-1's kept rows into srem (all 32 words), keep outputs
// 4-slot ring, full prefetch 2 ahead, ONE __syncthreads per iteration.
#define RSTRIDE 34  // u64 per row (32 data + 2 pad): 272B, 16B-aligned rows
__global__ __launch_bounds__(256) void k3_scan(float* __restrict__ out_keep)
{
    __shared__ __align__(16) unsigned long long buf[4][64][RSTRIDE];  // ~68KB
    __shared__ unsigned long long srem[32];
    __shared__ unsigned long long part[7][32];
    __shared__ unsigned long long skeep[2];
    __shared__ int ssidx[NP];  // 8KB

    const int b = blockIdx.x;
    const int tid = threadIdx.x;
    const int warp = tid >> 5, lane = tid & 31;

    for (int k = tid; k < NP; k += 256) ssidx[k] = g_sidx[b][k];
    if (tid < 32) srem[tid] = 0ull;
    if (tid == 0) { skeep[0] = 0ull; skeep[1] = 0ull; }

    // prefetch chunks 0 and 1 (row-padded copy: 1024 float4 each)
    #pragma unroll
    for (int ch = 0; ch < 2; ch++) {
        const float4* src = (const float4*)&g_mask[b][ch * 64][0];
        for (int v = tid; v < 1024; v += 256) {
            int row = v >> 4, col = v & 15;
            float4* dst = (float4*)&buf[ch][row][0] + col;
            unsigned sa = (unsigned)__cvta_generic_to_shared(dst);
            asm volatile("cp.async.cg.shared.global [%0], [%1], 16;\n"
                         :: "r"(sa), "l"(src + v) : "memory");
        }
        asm volatile("cp.async.commit_group;\n" ::: "memory");
    }
    asm volatile("cp.async.wait_group 1;\n" ::: "memory");  // chunk 0 retired

    for (int c = 0; c < 32; c++) {
        __syncthreads();  // chunk c visible; prev OR & keep published; ring slot free

        // prefetch chunk c+2 into slot (c+2)&3 (slot's old data = chunk c-2, done)
        if (c < 30) {
            const float4* src = (const float4*)&g_mask[b][(c + 2) * 64][0];
            const int slot = (c + 2) & 3;
            for (int v = tid; v < 1024; v += 256) {
                int row = v >> 4, col = v & 15;
                float4* dst = (float4*)&buf[slot][row][0] + col;
                unsigned sa = (unsigned)__cvta_generic_to_shared(dst);
                asm volatile("cp.async.cg.shared.global [%0], [%1], 16;\n"
                             :: "r"(sa), "l"(src + v) : "memory");
            }
        }
        asm volatile("cp.async.commit_group;\n" ::: "memory");  // always (maybe empty)

        const int cur = c & 3, prv = (c + 3) & 3;
        const unsigned long long kprev = skeep[(c & 1) ^ 1];  // chunk c-1 keep (0 for c=0)

        if (warp == 0) {
            // forward word: chunk c-1 kept rows' contribution to removed word c
            unsigned long long m0 = (unsigned long long)(-(long long)((kprev >> lane) & 1ull));
            unsigned long long m1 = (unsigned long long)(-(long long)((kprev >> (lane + 32)) & 1ull));
            unsigned long long f = (buf[prv][lane][c] & m0) | (buf[prv][lane + 32][c] & m1);
            // REDUX.OR on both halves (replaces 5-deep shfl butterfly)
            unsigned flo = __reduce_or_sync(0xFFFFFFFFu, (unsigned)f);
            unsigned fhi = __reduce_or_sync(0xFFFFFFFFu, (unsigned)(f >> 32));

            if (lane == 0) {
                unsigned Dlo[32], Dhi[64];
                #pragma unroll
                for (int r = 0; r < 32; r++) {
                    unsigned long long d = buf[cur][r][c];
                    Dlo[r] = (unsigned)d;
                    Dhi[r] = (unsigned)(d >> 32);
                }
                #pragma unroll
                for (int r = 32; r < 64; r++)
                    Dhi[r] = (unsigned)(buf[cur][r][c] >> 32);

                unsigned long long fw = ((unsigned long long)fhi << 32) | flo;
                unsigned long long rm = srem[c] | fw;  // concurrent srem[c] update is
                                                       // benign: only adds bits == fw
                unsigned lo = ~(unsigned)rm;
                unsigned hi = ~(unsigned)(rm >> 32);
                unsigned klo = 0, khi = 0;
                #pragma unroll
                for (int r = 0; r < 32; r++) {
                    unsigned s = (unsigned)((int)(lo << (31 - r)) >> 31);
                    klo |= s & (1u << r);
                    lo &= ~(Dlo[r] & s);
                    hi &= ~(Dhi[r] & s);
                }
                #pragma unroll
                for (int r = 0; r < 32; r++) {
                    unsigned s = (unsigned)((int)(hi << (31 - r)) >> 31);
                    khi |= s & (1u << r);
                    hi &= ~(Dhi[32 + r] & s);
                }
                skeep[c & 1] = ((unsigned long long)khi << 32) | klo;
            }
        } else {
            // OR phase for chunk c-1 (kprev==0 at c==0 -> no-op content-wise)
            const int w = warp - 1;  // 0..6
            unsigned long long p = 0ull;
            for (int r = w; r < 64; r += 7) {
                unsigned long long m =
                    (unsigned long long)(-(long long)((kprev >> r) & 1ull));
                p |= buf[prv][r][lane] & m;
            }
            part[w][lane] = p;
            asm volatile("bar.sync 1, 224;" ::: "memory");
            if (warp == 1) {
                srem[lane] |= (part[0][lane] | part[1][lane]) |
                              (part[2][lane] | part[3][lane]) |
                              (part[4][lane] | part[5][lane]) | part[6][lane];
            }
            if (warp == 2 && c > 0) {
                int row = (c - 1) * 64 + lane;
                int oi = ssidx[row];
                unsigned bit = (unsigned)((kprev >> lane) & 1ull);
                g_keep[b * NP + oi] = (unsigned char)bit;
                out_keep[b * NP + oi] = bit ? 1.0f : 0.0f;
                int row2 = row + 32;
                int oi2 = ssidx[row2];
                unsigned bit2 = (unsigned)((kprev >> (lane + 32)) & 1ull);
                g_keep[b * NP + oi2] = (unsigned char)bit2;
                out_keep[b * NP + oi2] = bit2 ? 1.0f : 0.0f;
            }
        }
        asm volatile("cp.async.wait_group 1;\n" ::: "memory");  // retire chunk c+1's group
    }
    __syncthreads();
    if (tid < 64) {  // outputs for chunk 31 (skeep[31&1] = skeep[1])
        unsigned long long k31 = skeep[1];
        int row = 31 * 64 + tid;
        int oi = ssidx[row];
        unsigned bit = (unsigned)((k31 >> tid) & 1ull);
        g_keep[b * NP + oi] = (unsigned char)bit;
        out_keep[b * NP + oi] = bit ? 1.0f : 0.0f;
    }
}

// ---------------- K4: apply keep mask, 2 independent float4 per thread ----------------
// out layout (floats): centers @0 (49152) | features @49152 (16777216) |
//                      cls @16826368 (49152) | keep @16875520 (16384, written by K3)
__global__ __launch_bounds__(256) void k4_apply(const float* __restrict__ centers,
                                                const float* __restrict__ features,
                                                const float* __restrict__ cls,
                                                float* __restrict__ out)
{
    const int NF4h = NB * NP * NCF / 8;  // 2097152: half the float4 tasks
    int t = blockIdx.x * 256 + threadIdx.x;
    if (t < NF4h) {
        int t2 = t + NF4h;
        bool k1 = g_keep[t >> 8] != 0;    // block maps to one point -> uniform
        bool k2 = g_keep[t2 >> 8] != 0;
        float4 v1 = make_float4(0.f, 0.f, 0.f, 0.f);
        float4 v2 = make_float4(0.f, 0.f, 0.f, 0.f);
        if (k1) v1 = __ldcs(((const float4*)features) + t);
        if (k2) v2 = __ldcs(((const float4*)features) + t2);
        __stcs(((float4*)out) + 12288 + t, v1);   // 49152/4 offset
        __stcs(((float4*)out) + 12288 + t2, v2);
    } else {
        int s = t - NF4h;
        if (s < NB * NP * 3) {
            int pg = s / 3;
            out[s] = g_keep[pg] ? centers[s] : 0.0f;
        } else {
            int e = s - NB * NP * 3;
            int pg = e / 3;
            out[16826368 + e] = g_keep[pg] ? cls[e] : 0.0f;
        }
    }
}

extern "C" void kernel_launch(void* const* d_in, const int* in_sizes, int n_in,
                              void* d_out, int out_size)
{
    const float* centers  = (const float*)d_in[0];
    const float* features = (const float*)d_in[1];
    const float* cls      = (const float*)d_in[2];
    const float* radius   = (const float*)d_in[3];
    float* out = (float*)d_out;

    k1_rank<<<dim3(64, NB), 256>>>(centers, cls, radius);
    k2_mask<<<dim3(32, NB), 256>>>();
    k3_scan<<<NB, 256>>>(out + 16875520);
    const int total = NB * NP * NCF / 8 + 2 * NB * NP * 3;  // 2195456
    k4_apply<<<total / 256, 256>>>(centers, features, cls, out);
}